// round 15
// baseline (speedup 1.0000x reference)
#include <cuda_runtime.h>
#include <cuda_bf16.h>
#include <math.h>
#include <stdint.h>

#define Vv 34004
#define Ee 300
#define Hh 512
#define Bb 64
#define Tt 512
#define G4H 2048
#define BH (Bb * Hh)
#define MK 32768          // M total = B*T
#define KPAD 320          // K padded to 320

// ---------------- scratch (device globals; no runtime allocation) ----------------
__device__ float g_xzf[67108864];          // [T][B][4H] fw pre-activations
__device__ float g_xzb[67108864];          // [T][B][4H] bw pre-activations (scan order)
__device__ __nv_bfloat16 g_hh[2 * 2 * BH]; // h hi split, ping-pong [buf][dir][b][H]
__device__ __nv_bfloat16 g_hl[2 * 2 * BH]; // h lo split
__device__ unsigned g_bar4[4];             // per-(dir,batch-group) barrier counters
__device__ __nv_bfloat16 g_Ah[(size_t)MK * KPAD];   // emb-gathered A, hi split
__device__ __nv_bfloat16 g_Al[(size_t)MK * KPAD];   // lo split
__device__ __nv_bfloat16 g_Bh[(size_t)4096 * KPAD]; // W^T (B[n][k]), hi split (fw||bw)
__device__ __nv_bfloat16 g_Bl[(size_t)4096 * KPAD];

// ---------------- PTX helpers (sm_80-class: compile under compute_103) ----------
__device__ __forceinline__ uint32_t smem_u32(const void* p) {
    uint32_t a;
    asm("{ .reg .u64 t; cvta.to.shared.u64 t, %1; cvt.u32.u64 %0, t; }"
        : "=r"(a) : "l"(p));
    return a;
}
#define CP_ASYNC16(s, g) \
    asm volatile("cp.async.cg.shared.global [%0], [%1], 16;" :: "r"(s), "l"(g))
#define CP_COMMIT() asm volatile("cp.async.commit_group;" ::: "memory")
#define CP_WAIT1()  asm volatile("cp.async.wait_group 1;" ::: "memory")
#define CP_WAIT0()  asm volatile("cp.async.wait_group 0;" ::: "memory")

#define LDSM4(r0, r1, r2, r3, addr) \
    asm volatile("ldmatrix.sync.aligned.m8n8.x4.shared.b16 {%0,%1,%2,%3}, [%4];" \
                 : "=r"(r0), "=r"(r1), "=r"(r2), "=r"(r3) : "r"(addr))

#define MMA16816(c, a0, a1, a2, a3, b0, b1) \
    asm volatile("mma.sync.aligned.m16n8k16.row.col.f32.bf16.bf16.f32 " \
                 "{%0,%1,%2,%3},{%4,%5,%6,%7},{%8,%9},{%0,%1,%2,%3};" \
                 : "+f"((c)[0]), "+f"((c)[1]), "+f"((c)[2]), "+f"((c)[3]) \
                 : "r"(a0), "r"(a1), "r"(a2), "r"(a3), "r"(b0), "r"(b1))

// =================================================================================
// prep_A: gather emb rows, split fp32 -> bf16 hi/lo, pad K to 320
// =================================================================================
__global__ void prep_A(const int* __restrict__ tokens, const float* __restrict__ emb) {
    size_t idx = (size_t)blockIdx.x * blockDim.x + threadIdx.x;
    if (idx >= (size_t)MK * KPAD) return;
    int m = (int)(idx / KPAD), k = (int)(idx - (size_t)m * KPAD);
    int t = m >> 6, b = m & 63;
    int tok = tokens[b * Tt + t];
    float v = (k < Ee) ? emb[(size_t)tok * Ee + k] : 0.f;
    __nv_bfloat16 hi = __float2bfloat16(v);
    g_Ah[idx] = hi;
    g_Al[idx] = __float2bfloat16(v - __bfloat162float(hi));
}

// =================================================================================
// prep_B: B[n][k] = W[k][n] (fw n<2048, bw n>=2048), split hi/lo, pad K to 320
// =================================================================================
__global__ void prep_B(const float* __restrict__ W_fw, const float* __restrict__ W_bw) {
    size_t idx = (size_t)blockIdx.x * blockDim.x + threadIdx.x;
    if (idx >= (size_t)4096 * KPAD) return;
    int n = (int)(idx / KPAD), k = (int)(idx - (size_t)n * KPAD);
    int dir = n >> 11, nn = n & 2047;
    const float* W = dir ? W_bw : W_fw;
    float v = (k < Ee) ? W[(size_t)k * G4H + nn] : 0.f;
    __nv_bfloat16 hi = __float2bfloat16(v);
    g_Bh[idx] = hi;
    g_Bl[idx] = __float2bfloat16(v - __bfloat162float(hi));
}

// =================================================================================
// gemm_hmma v2 (measured best: 856us): BM=128, BN=128, 512 threads,
// 16 warps as 4m x 4n, warp tile 32x32. K=320 in 5 chunks, cp.async dbl-buffered.
// =================================================================================
#define KC 64
#define SROW 144
#define SZT (128 * SROW)
#define OFF_AH 0
#define OFF_AL SZT
#define OFF_BH (2 * SZT)
#define OFF_BL (3 * SZT)
#define BUFSZ (4 * SZT)
#define GEMM_SMEM (2 * BUFSZ)

__global__ __launch_bounds__(512, 1) void gemm_hmma(
    const float* __restrict__ b_fw, const float* __restrict__ b_bw)
{
    extern __shared__ char smg[];
    const uint32_t base = smem_u32(smg);

    const int tid  = threadIdx.x;
    const int wid  = tid >> 5;
    const int lane = tid & 31;
    const int n0 = blockIdx.x * 128;
    const int m0 = blockIdx.y * 128;

    const int mw = (wid >> 2) * 32;
    const int nw = (wid & 3) * 32;

    const int lrow = tid >> 2;
    const int lg0  = (tid & 3) * 2;

    auto load_chunk = [&](int ch, int buf) {
        const int k0 = ch * KC;
        const uint32_t bb = base + buf * BUFSZ;
        const uint32_t sd = bb + lrow * SROW + lg0 * 16;
        {
            const size_t gsrc = (size_t)(m0 + lrow) * KPAD + k0 + lg0 * 8;
#pragma unroll
            for (int u = 0; u < 2; u++) {
                CP_ASYNC16(sd + OFF_AH + u * 16, g_Ah + gsrc + u * 8);
                CP_ASYNC16(sd + OFF_AL + u * 16, g_Al + gsrc + u * 8);
            }
        }
        {
            const size_t gsrc = (size_t)(n0 + lrow) * KPAD + k0 + lg0 * 8;
#pragma unroll
            for (int u = 0; u < 2; u++) {
                CP_ASYNC16(sd + OFF_BH + u * 16, g_Bh + gsrc + u * 8);
                CP_ASYNC16(sd + OFF_BL + u * 16, g_Bl + gsrc + u * 8);
            }
        }
        CP_COMMIT();
    };

    float acc[8][4];
#pragma unroll
    for (int i = 0; i < 8; i++)
#pragma unroll
        for (int j = 0; j < 4; j++) acc[i][j] = 0.f;

    const uint32_t a_off = (uint32_t)((lane & 15) * SROW + (lane >> 4) * 16);
    const uint32_t b_off = (uint32_t)(((lane & 7) + ((lane >> 4) & 1) * 8) * SROW
                                      + ((lane >> 3) & 1) * 16);

    load_chunk(0, 0);

    const int NCH = KPAD / KC;
    for (int ch = 0; ch < NCH; ch++) {
        const int buf = ch & 1;
        if (ch + 1 < NCH) {
            load_chunk(ch + 1, (ch + 1) & 1);
            CP_WAIT1();
        } else {
            CP_WAIT0();
        }
        __syncthreads();

        const uint32_t bb = base + buf * BUFSZ;
        const uint32_t aH = bb + OFF_AH + mw * SROW + a_off;
        const uint32_t aL = bb + OFF_AL + mw * SROW + a_off;
        const uint32_t bH = bb + OFF_BH + nw * SROW + b_off;
        const uint32_t bL = bb + OFF_BL + nw * SROW + b_off;

#pragma unroll
        for (int ks = 0; ks < KC / 16; ks++) {
            const uint32_t kb = ks * 32;
            uint32_t ah0[4], ah1[4], al0[4], al1[4];
            LDSM4(ah0[0], ah0[1], ah0[2], ah0[3], aH + kb);
            LDSM4(ah1[0], ah1[1], ah1[2], ah1[3], aH + 16 * SROW + kb);
            LDSM4(al0[0], al0[1], al0[2], al0[3], aL + kb);
            LDSM4(al1[0], al1[1], al1[2], al1[3], aL + 16 * SROW + kb);
            uint32_t bh[8], bl[8];
            LDSM4(bh[0], bh[1], bh[2], bh[3], bH + kb);
            LDSM4(bh[4], bh[5], bh[6], bh[7], bH + 16 * SROW + kb);
            LDSM4(bl[0], bl[1], bl[2], bl[3], bL + kb);
            LDSM4(bl[4], bl[5], bl[6], bl[7], bL + 16 * SROW + kb);

#pragma unroll
            for (int mi = 0; mi < 2; mi++) {
                const uint32_t* ah = mi ? ah1 : ah0;
                const uint32_t* al = mi ? al1 : al0;
#pragma unroll
                for (int ni = 0; ni < 4; ni++) {
                    float* c = acc[mi * 4 + ni];
                    const uint32_t bh0 = bh[ni * 2], bh1 = bh[ni * 2 + 1];
                    const uint32_t bl0 = bl[ni * 2], bl1 = bl[ni * 2 + 1];
                    MMA16816(c, ah[0], ah[1], ah[2], ah[3], bh0, bh1);
                    MMA16816(c, ah[0], ah[1], ah[2], ah[3], bl0, bl1);
                    MMA16816(c, al[0], al[1], al[2], al[3], bh0, bh1);
                }
            }
        }
        __syncthreads();
    }

    const int dir = n0 >> 11;
    const int nn0 = n0 & 2047;
    const float* bias = dir ? b_bw : b_fw;
    const int qr = lane >> 2;
    const int qc = (lane & 3) * 2;

#pragma unroll
    for (int mi = 0; mi < 2; mi++) {
#pragma unroll
        for (int ni = 0; ni < 4; ni++) {
            const float* c = acc[mi * 4 + ni];
            const int ncol = nw + ni * 8 + qc;
            const float bv0 = bias[nn0 + ncol];
            const float bv1 = bias[nn0 + ncol + 1];
#pragma unroll
            for (int half = 0; half < 2; half++) {
                const int m = m0 + mw + mi * 16 + qr + half * 8;
                const int t = m >> 6, b = m & 63;
                float* dst = dir
                    ? (g_xzb + ((size_t)(Tt - 1 - t) * Bb + b) * G4H + nn0 + ncol)
                    : (g_xzf + (size_t)m * G4H + nn0 + ncol);
                float2 o;
                o.x = c[half * 2 + 0] + bv0;
                o.y = c[half * 2 + 1] + bv1;
                *(float2*)dst = o;
            }
        }
    }
}

// =================================================================================
// init: reset barriers, seed h buf0 hi/lo from h0 ([b][H] layout = input layout)
// =================================================================================
__global__ void init_kernel(const float* __restrict__ h0_fw,
                            const float* __restrict__ h0_bw)
{
    int i = blockIdx.x * blockDim.x + threadIdx.x;
    if (i < 4) g_bar4[i] = 0u;
    if (i < BH) {
        float vf = h0_fw[i], vb = h0_bw[i];
        __nv_bfloat16 hf = __float2bfloat16(vf);
        __nv_bfloat16 hb = __float2bfloat16(vb);
        g_hh[i]      = hf;
        g_hl[i]      = __float2bfloat16(vf - __bfloat162float(hf));
        g_hh[BH + i] = hb;
        g_hl[BH + i] = __float2bfloat16(vb - __bfloat162float(hb));
    }
}

__device__ __forceinline__ float sigmoidf_fast(float x) {
    return __fdividef(1.f, 1.f + __expf(-x));
}
__device__ __forceinline__ float tanhf_fast(float x) {
    float xc = fminf(fmaxf(x, -15.f), 15.f);
    float e = __expf(2.f * xc);
    return __fdividef(e - 1.f, e + 1.f);
}

// =================================================================================
// Phase B: persistent bidirectional LSTM scan — m32xn32 warp tile, 4 K-quarters.
// 128 CTAs: (dir, batch-group of 32, unit-group of 16). 8 warps = 1m x 2n x 4k.
// Per ks: 8 LDSM4 / 24 HMMA -> 170 B smem per MMA (was 256).
// z partials [4][32][80] fp32 ALIAS the h staging region (dead between MMA end
// and next-step staging; extra __syncthreads guards the handoff).
// SMEM: h hi [32][520bf16] @0, h lo @33280, U hi [64][520] @66560, U lo @133120,
//       c [512] @199680. z aliased @0. Total 201728 B.
// =================================================================================
#define HSTR 1040
#define S_HHI 0
#define S_HLO 33280
#define S_UHI 66560
#define S_ULO 133120
#define S_C   199680
#define SCAN_SMEM_BYTES 201728
#define ZST 80
#define ZQ 2560                         // 32*80 floats per k-quarter slab

__global__ __launch_bounds__(256, 1) void lstm_scan(
    const float* __restrict__ U_fw, const float* __restrict__ U_bw,
    const float* __restrict__ c0_fw, const float* __restrict__ c0_bw,
    float* __restrict__ out, float* __restrict__ hT, float* __restrict__ cT)
{
    extern __shared__ __align__(16) char sml[];
    const uint32_t base = smem_u32(sml);
    __nv_bfloat16* uhi = (__nv_bfloat16*)(sml + S_UHI);
    __nv_bfloat16* ulo = (__nv_bfloat16*)(sml + S_ULO);
    float* z_s = (float*)(sml + S_HHI);   // ALIASED over h staging region
    float* c_s = (float*)(sml + S_C);

    const int tid  = threadIdx.x;
    const int wid  = tid >> 5;
    const int lane = tid & 31;
    const int dir  = blockIdx.x >> 6;
    const int r    = blockIdx.x & 63;
    const int b0c  = (r >> 5) * 32;      // batch-group base (0 or 32)
    const int j0   = (r & 31) * 16;      // unit-group base (16 units)
    const int grp  = dir * 2 + (r >> 5); // barrier group (32 CTAs)

    const float* __restrict__ U  = dir ? U_bw : U_fw;
    const float* __restrict__ c0 = dir ? c0_bw : c0_fw;
    const float* __restrict__ xz = dir ? g_xzb : g_xzf;

    // persistent U slice: 64 cols (c = gate*16 + jj), split hi/lo, layout [c][k]
    for (int i = tid; i < 64 * 512; i += 256) {
        int c = i >> 9, k = i & 511;
        float v = U[(size_t)k * G4H + (c >> 4) * Hh + j0 + (c & 15)];
        __nv_bfloat16 hi = __float2bfloat16(v);
        uhi[c * 520 + k] = hi;
        ulo[c * 520 + k] = __float2bfloat16(v - __bfloat162float(hi));
    }
    for (int i = tid; i < 512; i += 256)
        c_s[i] = c0[(b0c + (i >> 4)) * Hh + j0 + (i & 15)];

    // warp roles: 1 m (32 rows) x 2 n (32 cols) x 4 K-quarters (128 k each)
    const int nwarp = wid & 1;
    const int kq    = wid >> 1;          // 0..3
    const uint32_t kofs = (uint32_t)kq * 256;   // 128 bf16 = 256 bytes

    const uint32_t aHi0 = base + S_HHI
        + (uint32_t)((lane & 15) * HSTR) + kofs + (lane >> 4) * 16;
    const uint32_t aHi1 = aHi0 + 16 * HSTR;
    const uint32_t aLo0 = aHi0 + (S_HLO - S_HHI);
    const uint32_t aLo1 = aHi1 + (S_HLO - S_HHI);
    const uint32_t rowB = (uint32_t)((lane & 7) + ((lane >> 4) & 1) * 8);
    const uint32_t bHi0 = base + S_UHI + (nwarp * 32 + rowB) * HSTR + kofs
                          + ((lane >> 3) & 1) * 16;
    const uint32_t bHi1 = bHi0 + 16 * HSTR;
    const uint32_t bLo0 = bHi0 + (S_ULO - S_UHI);
    const uint32_t bLo1 = bHi1 + (S_ULO - S_UHI);

    // gate-phase identities: p = b*16 + jj
    int gb[2], gj[2];
#pragma unroll
    for (int pp = 0; pp < 2; pp++) {
        int p = tid + pp * 256;
        gb[pp] = p >> 4;
        gj[pp] = p & 15;
    }
    const int qr = lane >> 2;
    const int qc = (lane & 3) * 2;

    // prefetch xz for step 0
    float xzr[2][4];
#pragma unroll
    for (int pp = 0; pp < 2; pp++) {
        const float* row = xz + (size_t)(b0c + gb[pp]) * G4H + j0 + gj[pp];
#pragma unroll
        for (int gt = 0; gt < 4; gt++)
            xzr[pp][gt] = __ldcs(row + gt * Hh);
    }

    for (int step = 0; step < Tt; step++) {
        const int rb = (step & 1) * 2 + dir;
        const int wb = ((step + 1) & 1) * 2 + dir;

        // stage this CTA's 32 h-rows hi/lo from L2 via cp.async (64 KB total)
        // (overwrites last step's aliased z — safe: gates already consumed it)
        {
            const __nv_bfloat16* srcH = g_hh + (size_t)rb * BH + (size_t)b0c * Hh;
            const __nv_bfloat16* srcL = g_hl + (size_t)rb * BH + (size_t)b0c * Hh;
#pragma unroll 4
            for (int i = tid; i < 2048; i += 256) {
                uint32_t d = (uint32_t)((i >> 6) * HSTR + (i & 63) * 16);
                CP_ASYNC16(base + S_HHI + d, srcH + i * 8);
                CP_ASYNC16(base + S_HLO + d, srcL + i * 8);
            }
            CP_COMMIT();
            CP_WAIT0();
        }
        __syncthreads();

        // z_partial = h[32 rows, kq] @ U[kq, nwarp's 32 cols]: 8 k16 steps,
        // 8 LDSM4 + 24 HMMA per ks, 8 accumulator chains
        float acc[2][4][4];
#pragma unroll
        for (int mi = 0; mi < 2; mi++)
#pragma unroll
            for (int i = 0; i < 4; i++)
#pragma unroll
                for (int j = 0; j < 4; j++) acc[mi][i][j] = 0.f;

#pragma unroll 2
        for (int ks = 0; ks < 8; ks++) {
            const uint32_t kb = (uint32_t)ks * 32;
            uint32_t ah0[4], ah1[4], al0[4], al1[4];
            uint32_t bh0[4], bh1[4], bl0[4], bl1[4];
            LDSM4(ah0[0], ah0[1], ah0[2], ah0[3], aHi0 + kb);
            LDSM4(ah1[0], ah1[1], ah1[2], ah1[3], aHi1 + kb);
            LDSM4(al0[0], al0[1], al0[2], al0[3], aLo0 + kb);
            LDSM4(al1[0], al1[1], al1[2], al1[3], aLo1 + kb);
            LDSM4(bh0[0], bh0[1], bh0[2], bh0[3], bHi0 + kb);
            LDSM4(bh1[0], bh1[1], bh1[2], bh1[3], bHi1 + kb);
            LDSM4(bl0[0], bl0[1], bl0[2], bl0[3], bLo0 + kb);
            LDSM4(bl1[0], bl1[1], bl1[2], bl1[3], bLo1 + kb);

#pragma unroll
            for (int mi = 0; mi < 2; mi++) {
                const uint32_t* ah = mi ? ah1 : ah0;
                const uint32_t* al = mi ? al1 : al0;
                MMA16816(acc[mi][0], ah[0], ah[1], ah[2], ah[3], bh0[0], bh0[1]);
                MMA16816(acc[mi][1], ah[0], ah[1], ah[2], ah[3], bh0[2], bh0[3]);
                MMA16816(acc[mi][2], ah[0], ah[1], ah[2], ah[3], bh1[0], bh1[1]);
                MMA16816(acc[mi][3], ah[0], ah[1], ah[2], ah[3], bh1[2], bh1[3]);

                MMA16816(acc[mi][0], ah[0], ah[1], ah[2], ah[3], bl0[0], bl0[1]);
                MMA16816(acc[mi][1], ah[0], ah[1], ah[2], ah[3], bl0[2], bl0[3]);
                MMA16816(acc[mi][2], ah[0], ah[1], ah[2], ah[3], bl1[0], bl1[1]);
                MMA16816(acc[mi][3], ah[0], ah[1], ah[2], ah[3], bl1[2], bl1[3]);

                MMA16816(acc[mi][0], al[0], al[1], al[2], al[3], bh0[0], bh0[1]);
                MMA16816(acc[mi][1], al[0], al[1], al[2], al[3], bh0[2], bh0[3]);
                MMA16816(acc[mi][2], al[0], al[1], al[2], al[3], bh1[0], bh1[1]);
                MMA16816(acc[mi][3], al[0], al[1], al[2], al[3], bh1[2], bh1[3]);
            }
        }

        // all warps done reading h before z (aliased) is written
        __syncthreads();

        // publish z partials: z_s[kq][row][col]
        {
            float* zh = z_s + kq * ZQ;
#pragma unroll
            for (int mi = 0; mi < 2; mi++) {
                const int r0 = mi * 16 + qr, r1 = r0 + 8;
#pragma unroll
                for (int i = 0; i < 4; i++) {
                    const int cb = nwarp * 32 + i * 8 + qc;
                    *(float2*)&zh[r0 * ZST + cb] =
                        make_float2(acc[mi][i][0], acc[mi][i][1]);
                    *(float2*)&zh[r1 * ZST + cb] =
                        make_float2(acc[mi][i][2], acc[mi][i][3]);
                }
            }
        }
        __syncthreads();

        // gates: 512 (b,jj) pairs, 2 per thread; reduce 4 k-quarter partials
#pragma unroll
        for (int pp = 0; pp < 2; pp++) {
            const int b = gb[pp], jj = gj[pp];
            const float* zp = z_s + b * ZST + jj;
            float zv[4];
#pragma unroll
            for (int gt = 0; gt < 4; gt++) {
                const float* q = zp + gt * 16;
                zv[gt] = xzr[pp][gt] + ((q[0] + q[ZQ]) + (q[2 * ZQ] + q[3 * ZQ]));
            }
            const int p = tid + pp * 256;
            float cold = c_s[p];
            float ig = sigmoidf_fast(zv[0]);
            float fg = sigmoidf_fast(zv[1]);
            float gg = tanhf_fast(zv[2]);
            float og = sigmoidf_fast(zv[3]);
            float cn = fg * cold + ig * gg;
            float hn = og * tanhf_fast(cn);
            c_s[p] = cn;
            const int j = j0 + jj;
            const int bglob = b0c + b;
            __nv_bfloat16 hi = __float2bfloat16(hn);
            g_hh[(size_t)wb * BH + bglob * Hh + j] = hi;
            g_hl[(size_t)wb * BH + bglob * Hh + j] =
                __float2bfloat16(hn - __bfloat162float(hi));
            int tout = dir ? (Tt - 1 - step) : step;
            out[((size_t)bglob * Tt + tout) * (2 * Hh) + dir * Hh + j] = hn;
            if (step == Tt - 1) {
                hT[bglob * 2 * Hh + dir * Hh + j] = hn;
                cT[bglob * 2 * Hh + dir * Hh + j] = cn;
            }
        }

        // prefetch next step's xz (DRAM latency hides behind barrier wait)
        if (step + 1 < Tt) {
#pragma unroll
            for (int pp = 0; pp < 2; pp++) {
                const float* row = xz + ((size_t)(step + 1) * Bb + b0c + gb[pp]) * G4H
                                   + j0 + gj[pp];
#pragma unroll
                for (int gt = 0; gt < 4; gt++)
                    xzr[pp][gt] = __ldcs(row + gt * Hh);
            }
        }

        // per-(dir,bg) group barrier: 32 CTAs (skip after final step)
        __syncthreads();
        if (step + 1 < Tt) {
            if (tid == 0) {
                asm volatile("red.release.gpu.global.add.u32 [%0], 1;"
                             :: "l"(&g_bar4[grp]) : "memory");
                unsigned target = (unsigned)(step + 1) * 32u;
                unsigned v;
                do {
                    asm volatile("ld.acquire.gpu.global.u32 %0, [%1];"
                                 : "=r"(v) : "l"(&g_bar4[grp]) : "memory");
                    if (v >= target) break;
                    __nanosleep(32);
                } while (true);
            }
            __syncthreads();
        }
    }
}

// =================================================================================
extern "C" void kernel_launch(void* const* d_in, const int* in_sizes, int n_in,
                              void* d_out, int out_size)
{
    const int*   tokens = (const int*)  d_in[0];
    const float* h0_fw  = (const float*)d_in[1];
    const float* c0_fw  = (const float*)d_in[2];
    const float* h0_bw  = (const float*)d_in[3];
    const float* c0_bw  = (const float*)d_in[4];
    const float* emb    = (const float*)d_in[5];
    const float* W_fw   = (const float*)d_in[6];
    const float* U_fw   = (const float*)d_in[7];
    const float* b_fw   = (const float*)d_in[8];
    const float* W_bw   = (const float*)d_in[9];
    const float* U_bw   = (const float*)d_in[10];
    const float* b_bw   = (const float*)d_in[11];

    float* out = (float*)d_out;                       // [B,T,2H]
    float* hT  = out + (size_t)Bb * Tt * 2 * Hh;      // [B,2H]
    float* cT  = hT + (size_t)Bb * 2 * Hh;            // [B,2H]

    // prep: split inputs to bf16 hi/lo scratch
    {
        size_t na = (size_t)MK * KPAD;
        prep_A<<<(unsigned)((na + 255) / 256), 256>>>(tokens, emb);
        size_t nb = (size_t)4096 * KPAD;
        prep_B<<<(unsigned)((nb + 255) / 256), 256>>>(W_fw, W_bw);
    }
    init_kernel<<<128, 256>>>(h0_fw, h0_bw);

    // tensor-core input GEMM (v2: 512 threads, measured best)
    cudaFuncSetAttribute(gemm_hmma, cudaFuncAttributeMaxDynamicSharedMemorySize,
                         GEMM_SMEM);
    gemm_hmma<<<dim3(32, 256), 512, GEMM_SMEM>>>(b_fw, b_bw);

    // persistent LSTM scan (m32n32 warp tile, 4 K-quarters, aliased z)
    cudaFuncSetAttribute(lstm_scan, cudaFuncAttributeMaxDynamicSharedMemorySize,
                         SCAN_SMEM_BYTES);
    lstm_scan<<<128, 256, SCAN_SMEM_BYTES>>>(U_fw, U_bw, c0_fw, c0_bw, out, hT, cT);
}

// round 16
// speedup vs baseline: 1.0488x; 1.0488x over previous
#include <cuda_runtime.h>
#include <cuda_bf16.h>
#include <math.h>
#include <stdint.h>

#define Vv 34004
#define Ee 300
#define Hh 512
#define Bb 64
#define Tt 512
#define G4H 2048
#define BH (Bb * Hh)
#define MK 32768          // M total = B*T
#define KPAD 320          // K padded to 320
#define K8 40             // KPAD / 8

// ---------------- scratch (device globals; no runtime allocation) ----------------
__device__ float g_xzf[67108864];          // [T][B][4H] fw pre-activations
__device__ float g_xzb[67108864];          // [T][B][4H] bw pre-activations (scan order)
__device__ __nv_bfloat16 g_hh[2 * 2 * BH]; // h hi split, ping-pong [buf][dir][b][H]
__device__ __nv_bfloat16 g_hl[2 * 2 * BH]; // h lo split
__device__ unsigned g_bar2[2];             // per-direction barrier counters
__device__ __nv_bfloat16 g_Ah[(size_t)MK * KPAD];   // emb-gathered A, hi split
__device__ __nv_bfloat16 g_Al[(size_t)MK * KPAD];   // lo split
__device__ __nv_bfloat16 g_Bh[(size_t)4096 * KPAD]; // W^T (B[n][k]), hi split (fw||bw)
__device__ __nv_bfloat16 g_Bl[(size_t)4096 * KPAD];

// ---------------- PTX helpers (sm_80-class: compile under compute_103) ----------
__device__ __forceinline__ uint32_t smem_u32(const void* p) {
    uint32_t a;
    asm("{ .reg .u64 t; cvta.to.shared.u64 t, %1; cvt.u32.u64 %0, t; }"
        : "=r"(a) : "l"(p));
    return a;
}
#define CP_ASYNC16(s, g) \
    asm volatile("cp.async.cg.shared.global [%0], [%1], 16;" :: "r"(s), "l"(g))
#define CP_COMMIT() asm volatile("cp.async.commit_group;" ::: "memory")
#define CP_WAIT1()  asm volatile("cp.async.wait_group 1;" ::: "memory")
#define CP_WAIT0()  asm volatile("cp.async.wait_group 0;" ::: "memory")

#define LDSM4(r0, r1, r2, r3, addr) \
    asm volatile("ldmatrix.sync.aligned.m8n8.x4.shared.b16 {%0,%1,%2,%3}, [%4];" \
                 : "=r"(r0), "=r"(r1), "=r"(r2), "=r"(r3) : "r"(addr))

#define MMA16816(c, a0, a1, a2, a3, b0, b1) \
    asm volatile("mma.sync.aligned.m16n8k16.row.col.f32.bf16.bf16.f32 " \
                 "{%0,%1,%2,%3},{%4,%5,%6,%7},{%8,%9},{%0,%1,%2,%3};" \
                 : "+f"((c)[0]), "+f"((c)[1]), "+f"((c)[2]), "+f"((c)[3]) \
                 : "r"(a0), "r"(a1), "r"(a2), "r"(a3), "r"(b0), "r"(b1))

// pack two bf16 (from floats, hi/lo split) into uint32 words
__device__ __forceinline__ void split2(float v0, float v1, uint32_t& hw, uint32_t& lw) {
    __nv_bfloat16 h0 = __float2bfloat16(v0);
    __nv_bfloat16 h1 = __float2bfloat16(v1);
    __nv_bfloat16 l0 = __float2bfloat16(v0 - __bfloat162float(h0));
    __nv_bfloat16 l1 = __float2bfloat16(v1 - __bfloat162float(h1));
    hw = (uint32_t)__bfloat16_as_ushort(h0) | ((uint32_t)__bfloat16_as_ushort(h1) << 16);
    lw = (uint32_t)__bfloat16_as_ushort(l0) | ((uint32_t)__bfloat16_as_ushort(l1) << 16);
}

// =================================================================================
// prep_A (vectorized): 8 elements/thread. 1.31M threads, float4 loads, uint4 stores.
// =================================================================================
__global__ void prep_A(const int* __restrict__ tokens, const float* __restrict__ emb) {
    int idx = blockIdx.x * blockDim.x + threadIdx.x;
    if (idx >= MK * K8) return;
    int m = idx / K8, k8 = idx - m * K8;
    int k = k8 * 8;
    int t = m >> 6, b = m & 63;
    int tok = tokens[b * Tt + t];

    float v[8];
    if (k + 8 <= Ee) {
        const float* src = emb + (size_t)tok * Ee + k;
        float4 a = *(const float4*)(src);
        float4 c = *(const float4*)(src + 4);
        v[0] = a.x; v[1] = a.y; v[2] = a.z; v[3] = a.w;
        v[4] = c.x; v[5] = c.y; v[6] = c.z; v[7] = c.w;
    } else {
#pragma unroll
        for (int u = 0; u < 8; u++)
            v[u] = (k + u < Ee) ? emb[(size_t)tok * Ee + k + u] : 0.f;
    }

    uint4 hv, lv;
    split2(v[0], v[1], hv.x, lv.x);
    split2(v[2], v[3], hv.y, lv.y);
    split2(v[4], v[5], hv.z, lv.z);
    split2(v[6], v[7], hv.w, lv.w);
    size_t dst = (size_t)m * KPAD + k;
    *(uint4*)(g_Ah + dst) = hv;
    *(uint4*)(g_Al + dst) = lv;
}

// =================================================================================
// prep_B (vectorized): thread = (k8, n) with n fastest -> W reads coalesced in n.
// =================================================================================
__global__ void prep_B(const float* __restrict__ W_fw, const float* __restrict__ W_bw) {
    int idx = blockIdx.x * blockDim.x + threadIdx.x;
    if (idx >= K8 * 4096) return;
    int k8 = idx >> 12, n = idx & 4095;
    int k = k8 * 8;
    int dir = n >> 11, nn = n & 2047;
    const float* W = dir ? W_bw : W_fw;

    float v[8];
#pragma unroll
    for (int u = 0; u < 8; u++)
        v[u] = (k + u < Ee) ? W[(size_t)(k + u) * G4H + nn] : 0.f;

    uint4 hv, lv;
    split2(v[0], v[1], hv.x, lv.x);
    split2(v[2], v[3], hv.y, lv.y);
    split2(v[4], v[5], hv.z, lv.z);
    split2(v[6], v[7], hv.w, lv.w);
    size_t dst = (size_t)n * KPAD + k;
    *(uint4*)(g_Bh + dst) = hv;
    *(uint4*)(g_Bl + dst) = lv;
}

// =================================================================================
// gemm_hmma v2 (measured best: 856us): BM=128, BN=128, 512 threads,
// 16 warps as 4m x 4n, warp tile 32x32. K=320 in 5 chunks, cp.async dbl-buffered.
// =================================================================================
#define KC 64
#define SROW 144
#define SZT (128 * SROW)
#define OFF_AH 0
#define OFF_AL SZT
#define OFF_BH (2 * SZT)
#define OFF_BL (3 * SZT)
#define BUFSZ (4 * SZT)
#define GEMM_SMEM (2 * BUFSZ)

__global__ __launch_bounds__(512, 1) void gemm_hmma(
    const float* __restrict__ b_fw, const float* __restrict__ b_bw)
{
    extern __shared__ char smg[];
    const uint32_t base = smem_u32(smg);

    const int tid  = threadIdx.x;
    const int wid  = tid >> 5;
    const int lane = tid & 31;
    const int n0 = blockIdx.x * 128;
    const int m0 = blockIdx.y * 128;

    const int mw = (wid >> 2) * 32;
    const int nw = (wid & 3) * 32;

    const int lrow = tid >> 2;
    const int lg0  = (tid & 3) * 2;

    auto load_chunk = [&](int ch, int buf) {
        const int k0 = ch * KC;
        const uint32_t bb = base + buf * BUFSZ;
        const uint32_t sd = bb + lrow * SROW + lg0 * 16;
        {
            const size_t gsrc = (size_t)(m0 + lrow) * KPAD + k0 + lg0 * 8;
#pragma unroll
            for (int u = 0; u < 2; u++) {
                CP_ASYNC16(sd + OFF_AH + u * 16, g_Ah + gsrc + u * 8);
                CP_ASYNC16(sd + OFF_AL + u * 16, g_Al + gsrc + u * 8);
            }
        }
        {
            const size_t gsrc = (size_t)(n0 + lrow) * KPAD + k0 + lg0 * 8;
#pragma unroll
            for (int u = 0; u < 2; u++) {
                CP_ASYNC16(sd + OFF_BH + u * 16, g_Bh + gsrc + u * 8);
                CP_ASYNC16(sd + OFF_BL + u * 16, g_Bl + gsrc + u * 8);
            }
        }
        CP_COMMIT();
    };

    float acc[8][4];
#pragma unroll
    for (int i = 0; i < 8; i++)
#pragma unroll
        for (int j = 0; j < 4; j++) acc[i][j] = 0.f;

    const uint32_t a_off = (uint32_t)((lane & 15) * SROW + (lane >> 4) * 16);
    const uint32_t b_off = (uint32_t)(((lane & 7) + ((lane >> 4) & 1) * 8) * SROW
                                      + ((lane >> 3) & 1) * 16);

    load_chunk(0, 0);

    const int NCH = KPAD / KC;
    for (int ch = 0; ch < NCH; ch++) {
        const int buf = ch & 1;
        if (ch + 1 < NCH) {
            load_chunk(ch + 1, (ch + 1) & 1);
            CP_WAIT1();
        } else {
            CP_WAIT0();
        }
        __syncthreads();

        const uint32_t bb = base + buf * BUFSZ;
        const uint32_t aH = bb + OFF_AH + mw * SROW + a_off;
        const uint32_t aL = bb + OFF_AL + mw * SROW + a_off;
        const uint32_t bH = bb + OFF_BH + nw * SROW + b_off;
        const uint32_t bL = bb + OFF_BL + nw * SROW + b_off;

#pragma unroll
        for (int ks = 0; ks < KC / 16; ks++) {
            const uint32_t kb = ks * 32;
            uint32_t ah0[4], ah1[4], al0[4], al1[4];
            LDSM4(ah0[0], ah0[1], ah0[2], ah0[3], aH + kb);
            LDSM4(ah1[0], ah1[1], ah1[2], ah1[3], aH + 16 * SROW + kb);
            LDSM4(al0[0], al0[1], al0[2], al0[3], aL + kb);
            LDSM4(al1[0], al1[1], al1[2], al1[3], aL + 16 * SROW + kb);
            uint32_t bh[8], bl[8];
            LDSM4(bh[0], bh[1], bh[2], bh[3], bH + kb);
            LDSM4(bh[4], bh[5], bh[6], bh[7], bH + 16 * SROW + kb);
            LDSM4(bl[0], bl[1], bl[2], bl[3], bL + kb);
            LDSM4(bl[4], bl[5], bl[6], bl[7], bL + 16 * SROW + kb);

#pragma unroll
            for (int mi = 0; mi < 2; mi++) {
                const uint32_t* ah = mi ? ah1 : ah0;
                const uint32_t* al = mi ? al1 : al0;
#pragma unroll
                for (int ni = 0; ni < 4; ni++) {
                    float* c = acc[mi * 4 + ni];
                    const uint32_t bh0 = bh[ni * 2], bh1 = bh[ni * 2 + 1];
                    const uint32_t bl0 = bl[ni * 2], bl1 = bl[ni * 2 + 1];
                    MMA16816(c, ah[0], ah[1], ah[2], ah[3], bh0, bh1);
                    MMA16816(c, ah[0], ah[1], ah[2], ah[3], bl0, bl1);
                    MMA16816(c, al[0], al[1], al[2], al[3], bh0, bh1);
                }
            }
        }
        __syncthreads();
    }

    const int dir = n0 >> 11;
    const int nn0 = n0 & 2047;
    const float* bias = dir ? b_bw : b_fw;
    const int qr = lane >> 2;
    const int qc = (lane & 3) * 2;

#pragma unroll
    for (int mi = 0; mi < 2; mi++) {
#pragma unroll
        for (int ni = 0; ni < 4; ni++) {
            const float* c = acc[mi * 4 + ni];
            const int ncol = nw + ni * 8 + qc;
            const float bv0 = bias[nn0 + ncol];
            const float bv1 = bias[nn0 + ncol + 1];
#pragma unroll
            for (int half = 0; half < 2; half++) {
                const int m = m0 + mw + mi * 16 + qr + half * 8;
                const int t = m >> 6, b = m & 63;
                float* dst = dir
                    ? (g_xzb + ((size_t)(Tt - 1 - t) * Bb + b) * G4H + nn0 + ncol)
                    : (g_xzf + (size_t)m * G4H + nn0 + ncol);
                float2 o;
                o.x = c[half * 2 + 0] + bv0;
                o.y = c[half * 2 + 1] + bv1;
                *(float2*)dst = o;
            }
        }
    }
}

// =================================================================================
// init: reset barriers, seed h buf0 hi/lo from h0 ([b][H] layout = input layout)
// =================================================================================
__global__ void init_kernel(const float* __restrict__ h0_fw,
                            const float* __restrict__ h0_bw)
{
    int i = blockIdx.x * blockDim.x + threadIdx.x;
    if (i < 2) g_bar2[i] = 0u;
    if (i < BH) {
        float vf = h0_fw[i], vb = h0_bw[i];
        __nv_bfloat16 hf = __float2bfloat16(vf);
        __nv_bfloat16 hb = __float2bfloat16(vb);
        g_hh[i]      = hf;
        g_hl[i]      = __float2bfloat16(vf - __bfloat162float(hf));
        g_hh[BH + i] = hb;
        g_hl[BH + i] = __float2bfloat16(vb - __bfloat162float(hb));
    }
}

__device__ __forceinline__ float sigmoidf_fast(float x) {
    return __fdividef(1.f, 1.f + __expf(-x));
}
__device__ __forceinline__ float tanhf_fast(float x) {
    float xc = fminf(fmaxf(x, -15.f), 15.f);
    float e = __expf(2.f * xc);
    return __fdividef(e - 1.f, e + 1.f);
}

// =================================================================================
// Phase B: persistent bidirectional LSTM scan — EXACT R12 structure (measured
// best: 2.42 ms scan) + final-step barrier skip as the only delta.
// 128 CTAs: (dir, batch-group of 32, unit-group of 16). 8 warps = 2m x 2n x 2k.
// =================================================================================
#define HSTR 1040
#define S_HHI 0
#define S_HLO 33280
#define S_UHI 66560
#define S_ULO 133120
#define S_Z   199680
#define S_C   220160
#define SCAN_SMEM_BYTES 222208
#define ZST 80
#define ZHALF 2560

__global__ __launch_bounds__(256, 1) void lstm_scan(
    const float* __restrict__ U_fw, const float* __restrict__ U_bw,
    const float* __restrict__ c0_fw, const float* __restrict__ c0_bw,
    float* __restrict__ out, float* __restrict__ hT, float* __restrict__ cT)
{
    extern __shared__ __align__(16) char sml[];
    const uint32_t base = smem_u32(sml);
    __nv_bfloat16* uhi = (__nv_bfloat16*)(sml + S_UHI);
    __nv_bfloat16* ulo = (__nv_bfloat16*)(sml + S_ULO);
    float* z_s = (float*)(sml + S_Z);
    float* c_s = (float*)(sml + S_C);

    const int tid  = threadIdx.x;
    const int wid  = tid >> 5;
    const int lane = tid & 31;
    const int dir  = blockIdx.x >> 6;
    const int r    = blockIdx.x & 63;
    const int b0c  = (r >> 5) * 32;      // batch-group base (0 or 32)
    const int j0   = (r & 31) * 16;      // unit-group base (16 units)

    const float* __restrict__ U  = dir ? U_bw : U_fw;
    const float* __restrict__ c0 = dir ? c0_bw : c0_fw;
    const float* __restrict__ xz = dir ? g_xzb : g_xzf;

    // persistent U slice: 64 cols (c = gate*16 + jj), split hi/lo, layout [c][k]
    for (int i = tid; i < 64 * 512; i += 256) {
        int c = i >> 9, k = i & 511;
        float v = U[(size_t)k * G4H + (c >> 4) * Hh + j0 + (c & 15)];
        __nv_bfloat16 hi = __float2bfloat16(v);
        uhi[c * 520 + k] = hi;
        ulo[c * 520 + k] = __float2bfloat16(v - __bfloat162float(hi));
    }
    for (int i = tid; i < 512; i += 256)
        c_s[i] = c0[(b0c + (i >> 4)) * Hh + j0 + (i & 15)];

    // warp roles: 2 m x 2 n x 2 k-halves
    const int mwarp = wid & 1;
    const int nwarp = (wid >> 1) & 1;
    const int khalf = wid >> 2;
    const uint32_t kofs = (uint32_t)khalf * 512;

    const uint32_t aHi = base + S_HHI
        + (uint32_t)((mwarp * 16 + (lane & 15)) * HSTR) + kofs + (lane >> 4) * 16;
    const uint32_t aLo = aHi + (S_HLO - S_HHI);
    const uint32_t rowB = (uint32_t)((lane & 7) + ((lane >> 4) & 1) * 8);
    const uint32_t bHi0 = base + S_UHI + (nwarp * 32 + rowB) * HSTR + kofs
                          + ((lane >> 3) & 1) * 16;
    const uint32_t bHi1 = bHi0 + 16 * HSTR;
    const uint32_t bLo0 = bHi0 + (S_ULO - S_UHI);
    const uint32_t bLo1 = bHi1 + (S_ULO - S_UHI);

    // gate-phase identities: p = b*16 + jj
    int gb[2], gj[2];
#pragma unroll
    for (int pp = 0; pp < 2; pp++) {
        int p = tid + pp * 256;
        gb[pp] = p >> 4;
        gj[pp] = p & 15;
    }
    const int qr = lane >> 2;
    const int qc = (lane & 3) * 2;

    // prefetch xz for step 0
    float xzr[2][4];
#pragma unroll
    for (int pp = 0; pp < 2; pp++) {
        const float* row = xz + (size_t)(b0c + gb[pp]) * G4H + j0 + gj[pp];
#pragma unroll
        for (int gt = 0; gt < 4; gt++)
            xzr[pp][gt] = __ldcs(row + gt * Hh);
    }

    for (int step = 0; step < Tt; step++) {
        const int rb = (step & 1) * 2 + dir;
        const int wb = ((step + 1) & 1) * 2 + dir;

        // stage this CTA's 32 h-rows hi/lo from L2 via cp.async (64 KB total)
        {
            const __nv_bfloat16* srcH = g_hh + (size_t)rb * BH + (size_t)b0c * Hh;
            const __nv_bfloat16* srcL = g_hl + (size_t)rb * BH + (size_t)b0c * Hh;
#pragma unroll 4
            for (int i = tid; i < 2048; i += 256) {
                uint32_t d = (uint32_t)((i >> 6) * HSTR + (i & 63) * 16);
                CP_ASYNC16(base + S_HHI + d, srcH + i * 8);
                CP_ASYNC16(base + S_HLO + d, srcL + i * 8);
            }
            CP_COMMIT();
            CP_WAIT0();
        }
        __syncthreads();

        // z_partial = h[16 rows, khalf] @ U[khalf, 32 cols]: 16 k16 steps
        float acc[4][4];
#pragma unroll
        for (int i = 0; i < 4; i++)
#pragma unroll
            for (int j = 0; j < 4; j++) acc[i][j] = 0.f;

#pragma unroll 4
        for (int ks = 0; ks < 16; ks++) {
            const uint32_t kb = (uint32_t)ks * 32;
            uint32_t ah[4], al[4], bh0[4], bh1[4], bl0[4], bl1[4];
            LDSM4(ah[0], ah[1], ah[2], ah[3], aHi + kb);
            LDSM4(al[0], al[1], al[2], al[3], aLo + kb);
            LDSM4(bh0[0], bh0[1], bh0[2], bh0[3], bHi0 + kb);
            LDSM4(bh1[0], bh1[1], bh1[2], bh1[3], bHi1 + kb);
            LDSM4(bl0[0], bl0[1], bl0[2], bl0[3], bLo0 + kb);
            LDSM4(bl1[0], bl1[1], bl1[2], bl1[3], bLo1 + kb);

            MMA16816(acc[0], ah[0], ah[1], ah[2], ah[3], bh0[0], bh0[1]);
            MMA16816(acc[1], ah[0], ah[1], ah[2], ah[3], bh0[2], bh0[3]);
            MMA16816(acc[2], ah[0], ah[1], ah[2], ah[3], bh1[0], bh1[1]);
            MMA16816(acc[3], ah[0], ah[1], ah[2], ah[3], bh1[2], bh1[3]);

            MMA16816(acc[0], ah[0], ah[1], ah[2], ah[3], bl0[0], bl0[1]);
            MMA16816(acc[1], ah[0], ah[1], ah[2], ah[3], bl0[2], bl0[3]);
            MMA16816(acc[2], ah[0], ah[1], ah[2], ah[3], bl1[0], bl1[1]);
            MMA16816(acc[3], ah[0], ah[1], ah[2], ah[3], bl1[2], bl1[3]);

            MMA16816(acc[0], al[0], al[1], al[2], al[3], bh0[0], bh0[1]);
            MMA16816(acc[1], al[0], al[1], al[2], al[3], bh0[2], bh0[3]);
            MMA16816(acc[2], al[0], al[1], al[2], al[3], bh1[0], bh1[1]);
            MMA16816(acc[3], al[0], al[1], al[2], al[3], bh1[2], bh1[3]);
        }

        // publish z partials: z_s[khalf][row][col]
        {
            float* zh = z_s + khalf * ZHALF;
            const int r0 = mwarp * 16 + qr, r1 = r0 + 8;
#pragma unroll
            for (int i = 0; i < 4; i++) {
                const int cb = nwarp * 32 + i * 8 + qc;
                *(float2*)&zh[r0 * ZST + cb] = make_float2(acc[i][0], acc[i][1]);
                *(float2*)&zh[r1 * ZST + cb] = make_float2(acc[i][2], acc[i][3]);
            }
        }
        __syncthreads();

        // gates: 512 (b,jj) pairs, 2 per thread; reduce the 2 K-half partials
#pragma unroll
        for (int pp = 0; pp < 2; pp++) {
            const int b = gb[pp], jj = gj[pp];
            const float* z1 = z_s + b * ZST + jj;
            const float* z2 = z1 + ZHALF;
            float zi = xzr[pp][0] + z1[0]  + z2[0];
            float zf = xzr[pp][1] + z1[16] + z2[16];
            float zg = xzr[pp][2] + z1[32] + z2[32];
            float zo = xzr[pp][3] + z1[48] + z2[48];
            const int p = tid + pp * 256;
            float cold = c_s[p];
            float ig = sigmoidf_fast(zi);
            float fg = sigmoidf_fast(zf);
            float gg = tanhf_fast(zg);
            float og = sigmoidf_fast(zo);
            float cn = fg * cold + ig * gg;
            float hn = og * tanhf_fast(cn);
            c_s[p] = cn;
            const int j = j0 + jj;
            const int bglob = b0c + b;
            __nv_bfloat16 hi = __float2bfloat16(hn);
            g_hh[(size_t)wb * BH + bglob * Hh + j] = hi;
            g_hl[(size_t)wb * BH + bglob * Hh + j] =
                __float2bfloat16(hn - __bfloat162float(hi));
            int tout = dir ? (Tt - 1 - step) : step;
            out[((size_t)bglob * Tt + tout) * (2 * Hh) + dir * Hh + j] = hn;
            if (step == Tt - 1) {
                hT[bglob * 2 * Hh + dir * Hh + j] = hn;
                cT[bglob * 2 * Hh + dir * Hh + j] = cn;
            }
        }

        // prefetch next step's xz (DRAM latency hides behind barrier wait)
        if (step + 1 < Tt) {
#pragma unroll
            for (int pp = 0; pp < 2; pp++) {
                const float* row = xz + ((size_t)(step + 1) * Bb + b0c + gb[pp]) * G4H
                                   + j0 + gj[pp];
#pragma unroll
                for (int gt = 0; gt < 4; gt++)
                    xzr[pp][gt] = __ldcs(row + gt * Hh);
            }
        }

        // per-direction grid barrier (skip after final step)
        __syncthreads();
        if (step + 1 < Tt) {
            if (tid == 0) {
                asm volatile("red.release.gpu.global.add.u32 [%0], 1;"
                             :: "l"(&g_bar2[dir]) : "memory");
                unsigned target = (unsigned)(step + 1) * 64u;
                unsigned v;
                do {
                    asm volatile("ld.acquire.gpu.global.u32 %0, [%1];"
                                 : "=r"(v) : "l"(&g_bar2[dir]) : "memory");
                    if (v >= target) break;
                    __nanosleep(32);
                } while (true);
            }
            __syncthreads();
        }
    }
}

// =================================================================================
extern "C" void kernel_launch(void* const* d_in, const int* in_sizes, int n_in,
                              void* d_out, int out_size)
{
    const int*   tokens = (const int*)  d_in[0];
    const float* h0_fw  = (const float*)d_in[1];
    const float* c0_fw  = (const float*)d_in[2];
    const float* h0_bw  = (const float*)d_in[3];
    const float* c0_bw  = (const float*)d_in[4];
    const float* emb    = (const float*)d_in[5];
    const float* W_fw   = (const float*)d_in[6];
    const float* U_fw   = (const float*)d_in[7];
    const float* b_fw   = (const float*)d_in[8];
    const float* W_bw   = (const float*)d_in[9];
    const float* U_bw   = (const float*)d_in[10];
    const float* b_bw   = (const float*)d_in[11];

    float* out = (float*)d_out;                       // [B,T,2H]
    float* hT  = out + (size_t)Bb * Tt * 2 * Hh;      // [B,2H]
    float* cT  = hT + (size_t)Bb * 2 * Hh;            // [B,2H]

    // prep: split inputs to bf16 hi/lo scratch (vectorized, 8 elems/thread)
    prep_A<<<(MK * K8 + 255) / 256, 256>>>(tokens, emb);
    prep_B<<<(K8 * 4096 + 255) / 256, 256>>>(W_fw, W_bw);
    init_kernel<<<128, 256>>>(h0_fw, h0_bw);

    // tensor-core input GEMM (v2: 512 threads, measured best)
    cudaFuncSetAttribute(gemm_hmma, cudaFuncAttributeMaxDynamicSharedMemorySize,
                         GEMM_SMEM);
    gemm_hmma<<<dim3(32, 256), 512, GEMM_SMEM>>>(b_fw, b_bw);

    // persistent LSTM scan (exact R12 + final-barrier skip)
    cudaFuncSetAttribute(lstm_scan, cudaFuncAttributeMaxDynamicSharedMemorySize,
                         SCAN_SMEM_BYTES);
    lstm_scan<<<128, 256, SCAN_SMEM_BYTES>>>(U_fw, U_bw, c0_fw, c0_bw, out, hT, cT);
}